// round 2
// baseline (speedup 1.0000x reference)
#include <cuda_runtime.h>

#define M_PTS 5151
#define HIDN  256
#define BB    16
#define SS    256
#define TT    1024
#define NBLK_M 41          // ceil(5151/128) scan blocks per batch
#define CUT 0.018f

// Output layout: concatenated (b_out, density, m, initial_states, mesh)
#define OFF_BOUT 0
#define OFF_D    16384                    // 16*1024
#define OFF_M    (OFF_D + BB*M_PTS)       // 98800
#define OFF_IS   (OFF_M + BB*TT)          // 115184
#define OFF_MESH (OFF_IS + BB*M_PTS)      // 197600

// ---------------- scratch (device globals; no allocation) ----------------
__device__ float g_x[5248*HIDN];
__device__ float g_y[5248*HIDN];
__device__ float g_density[M_PTS];
__device__ float g_cwc[BB*HIDN];
__device__ float g_init[BB*M_PTS];
__device__ float g_bpart[BB*NBLK_M*TT];
__device__ float g_dsum;

__device__ __forceinline__ float fast_tanh(float x) {
    float r;
    asm("tanh.approx.f32 %0, %1;" : "=f"(r) : "f"(x));
    return r;
}

// ---------------- density input layer: x = relu(mesh @ Win + bin) --------
__global__ void k_dens_in(const float* __restrict__ mesh,
                          const float* __restrict__ Win,
                          const float* __restrict__ bin) {
    int m = blockIdx.x;
    int j = threadIdx.x;
    float be = mesh[2*m], al = mesh[2*m+1];
    float v = be*Win[j] + al*Win[HIDN+j] + bin[j];
    g_x[m*HIDN + j] = fmaxf(v, 0.f);
}

// ---------------- residual layer: Y = X + relu(X @ W + b) ----------------
// 128x64 tile, BK=8, 256 threads, 8x4 micro-tile.
__global__ void __launch_bounds__(256) k_res(const float* __restrict__ W,
                                             const float* __restrict__ bias,
                                             int flip) {
    const float* X = flip ? g_y : g_x;
    float*       Y = flip ? g_x : g_y;

    __shared__ __align__(16) float As[8][132];
    __shared__ __align__(16) float Bs[8][64];

    int bm = blockIdx.x * 128, bn = blockIdx.y * 64;
    int tid = threadIdx.x;
    int tx = tid & 15;        // col group (4 cols)
    int ty = tid >> 4;        // row group (8 rows)

    float acc[8][4];
#pragma unroll
    for (int i = 0; i < 8; i++)
#pragma unroll
        for (int j = 0; j < 4; j++) acc[i][j] = 0.f;

    int arow = tid >> 1;            // 0..127
    int acol = (tid & 1) * 4;       // 0 or 4
    int gra  = bm + arow;
    bool av  = gra < M_PTS;
    int bkr  = tid >> 4;            // (for tid<128) 0..7
    int bc   = (tid & 15) * 4;

    for (int k0 = 0; k0 < HIDN; k0 += 8) {
        float4 a4 = av ? *(const float4*)&X[gra*HIDN + k0 + acol]
                       : make_float4(0.f, 0.f, 0.f, 0.f);
        As[acol+0][arow] = a4.x;
        As[acol+1][arow] = a4.y;
        As[acol+2][arow] = a4.z;
        As[acol+3][arow] = a4.w;
        if (tid < 128)
            *(float4*)&Bs[bkr][bc] = *(const float4*)&W[(k0+bkr)*HIDN + bn + bc];
        __syncthreads();
#pragma unroll
        for (int kk = 0; kk < 8; kk++) {
            float4 a0 = *(const float4*)&As[kk][ty*8];
            float4 a1 = *(const float4*)&As[kk][ty*8 + 4];
            float4 b0 = *(const float4*)&Bs[kk][tx*4];
            float a[8] = {a0.x,a0.y,a0.z,a0.w,a1.x,a1.y,a1.z,a1.w};
            float b[4] = {b0.x,b0.y,b0.z,b0.w};
#pragma unroll
            for (int i = 0; i < 8; i++)
#pragma unroll
                for (int j = 0; j < 4; j++)
                    acc[i][j] = fmaf(a[i], b[j], acc[i][j]);
        }
        __syncthreads();
    }

    int gc0 = bn + tx*4;
    float4 bz = *(const float4*)&bias[gc0];
    float bv[4] = {bz.x, bz.y, bz.z, bz.w};
#pragma unroll
    for (int i = 0; i < 8; i++) {
        int gr = bm + ty*8 + i;
        if (gr < M_PTS) {
            float4 xv = *(const float4*)&X[gr*HIDN + gc0];
            float4 o;
            o.x = xv.x + fmaxf(acc[i][0] + bv[0], 0.f);
            o.y = xv.y + fmaxf(acc[i][1] + bv[1], 0.f);
            o.z = xv.z + fmaxf(acc[i][2] + bv[2], 0.f);
            o.w = xv.w + fmaxf(acc[i][3] + bv[3], 0.f);
            *(float4*)&Y[gr*HIDN + gc0] = o;
        }
    }
}

// ---------------- density output: sigmoid(x @ Wout + bout) ---------------
__global__ void k_dens_out(const float* __restrict__ Wout,
                           const float* __restrict__ bout) {
    int w = blockIdx.x*8 + (threadIdx.x >> 5);
    int lane = threadIdx.x & 31;
    if (w >= M_PTS) return;
    float acc = 0.f;
#pragma unroll
    for (int i = 0; i < 8; i++)
        acc += g_y[w*HIDN + lane + i*32] * Wout[lane + i*32];
#pragma unroll
    for (int o = 16; o; o >>= 1) acc += __shfl_xor_sync(0xffffffffu, acc, o);
    if (lane == 0) {
        float z = acc + bout[0];
        g_density[w] = 1.f / (1.f + __expf(-z));
    }
}

// ---------------- dsum (deterministic single-block reduce) ---------------
__global__ void k_dsum() {
    __shared__ float s[256];
    int tid = threadIdx.x;
    float a = 0.f;
    for (int i = tid; i < M_PTS; i += 256) a += g_density[i];
    s[tid] = a;
    __syncthreads();
    for (int o = 128; o; o >>= 1) {
        if (tid < o) s[tid] += s[tid + o];
        __syncthreads();
    }
    if (tid == 0) g_dsum = s[0];
}

// ---------------- encoder ctx + ctx @ Wc (fused) ----------------
__global__ void k_ctxw(const float* __restrict__ enc,
                       const float* __restrict__ mask,
                       const float* __restrict__ Ws,
                       const float* __restrict__ bs,
                       const float* __restrict__ Wc) {
    int b = blockIdx.x;
    int j = threadIdx.x;
    __shared__ float se[2*SS];
    __shared__ float sm[SS];
    __shared__ float sctx[HIDN];
    for (int i = j; i < 2*SS; i += 256) se[i] = enc[b*2*SS + i];
    for (int i = j; i < SS;   i += 256) sm[i] = mask[b*SS + i];
    __syncthreads();
    float w0 = Ws[j], w1 = Ws[HIDN + j], bj = bs[j];
    float acc = 0.f, msum = 0.f;
    for (int s = 0; s < SS; s++) {
        float mk = sm[s];
        msum += mk;
        float v = fmaxf(se[2*s]*w0 + se[2*s+1]*w1 + bj, 0.f);
        acc += mk * v;
    }
    sctx[j] = acc / fmaxf(msum, 1.f);
    __syncthreads();
    float a2 = 0.f;
    for (int k = 0; k < HIDN; k++) a2 += sctx[k] * Wc[k*HIDN + j];
    g_cwc[b*HIDN + j] = a2;
}

// ---------------- initial states + density/mesh output replication -------
__global__ void k_init(const float* __restrict__ mesh,
                       const float* __restrict__ Wm,
                       const float* __restrict__ bm,
                       const float* __restrict__ Wo,
                       const float* __restrict__ bo,
                       float* __restrict__ out) {
    int b = blockIdx.y;
    int j = threadIdx.x;
    __shared__ __align__(16) float sW0[HIDN], sW1[HIDN], sW2[HIDN], sWo[HIDN], sC[HIDN];
    sW0[j] = Wm[j];
    sW1[j] = Wm[HIDN + j];
    sW2[j] = Wm[2*HIDN + j];
    sWo[j] = Wo[j];
    sC[j]  = g_cwc[b*HIDN + j] + bm[j];
    __syncthreads();
    int m = blockIdx.x*256 + j;
    if (m >= M_PTS) return;
    float be = mesh[2*m], al = mesh[2*m+1], d = g_density[m];
    const float4* w0 = (const float4*)sW0;
    const float4* w1 = (const float4*)sW1;
    const float4* w2 = (const float4*)sW2;
    const float4* wo = (const float4*)sWo;
    const float4* cc = (const float4*)sC;
    float acc = 0.f;
#pragma unroll 4
    for (int q = 0; q < HIDN/4; q++) {
        float4 a0 = w0[q], a1 = w1[q], a2 = w2[q], ao = wo[q], ac = cc[q];
        acc += fmaxf(be*a0.x + al*a1.x + d*a2.x + ac.x, 0.f) * ao.x;
        acc += fmaxf(be*a0.y + al*a1.y + d*a2.y + ac.y, 0.f) * ao.y;
        acc += fmaxf(be*a0.z + al*a1.z + d*a2.z + ac.z, 0.f) * ao.z;
        acc += fmaxf(be*a0.w + al*a1.w + d*a2.w + ac.w, 0.f) * ao.w;
    }
    float is = tanhf(acc + bo[0]);
    g_init[b*M_PTS + m] = is;
    out[OFF_IS + (size_t)b*M_PTS + m] = is;
    // replicate density + mesh into output
    out[OFF_D + (size_t)b*M_PTS + m] = d;
    ((float2*)out)[(OFF_MESH >> 1) + (size_t)b*M_PTS + m] = make_float2(be, al);
}

// ---------------- relay scan: 64 threads, 2 points/thread ----------------
__global__ void k_scan(const float* __restrict__ dec,
                       const float* __restrict__ mesh) {
    __shared__ float sh_h[TT];
    __shared__ float sh_part[2][TT];
    int b = blockIdx.y;
    int tid = threadIdx.x;        // 0..63
    int m0 = blockIdx.x*128 + tid;
    int m1 = m0 + 64;

    for (int t = tid; t < TT; t += 64) sh_h[t] = dec[b*TT + t];

    bool v0 = m0 < M_PTS, v1 = m1 < M_PTS;
    float be0 = v0 ? mesh[2*m0]   : -2.f;
    float al0 = v0 ? mesh[2*m0+1] :  2.f;
    float d0  = v0 ? g_density[m0] : 0.f;
    float s0  = v0 ? g_init[b*M_PTS + m0] : 0.f;
    float be1 = v1 ? mesh[2*m1]   : -2.f;
    float al1 = v1 ? mesh[2*m1+1] :  2.f;
    float d1  = v1 ? g_density[m1] : 0.f;
    float s1  = v1 ? g_init[b*M_PTS + m1] : 0.f;
    __syncthreads();

    int wid = tid >> 5, lane = tid & 31;
    float* myrow = sh_part[wid];

    for (int t = 0; t < TT; t++) {
        float ht = sh_h[t];

        float xu0 = ht - al0;
        float xd0 = be0 - ht;
        if (__any_sync(0xffffffffu, (fabsf(xu0) < CUT) | (fabsf(xd0) < CUT))) {
            float wu = 0.5f*fast_tanh(500.f*xu0) + 0.5f;
            float wd = 0.5f*fast_tanh(500.f*xd0) + 0.5f;
            s0 += wu * (1.f - s0);
            s0 += wd * (-1.f - s0);
        } else {
            if (xu0 > 0.f) s0 = 1.f;
            if (xd0 > 0.f) s0 = -1.f;
        }

        float xu1 = ht - al1;
        float xd1 = be1 - ht;
        if (__any_sync(0xffffffffu, (fabsf(xu1) < CUT) | (fabsf(xd1) < CUT))) {
            float wu = 0.5f*fast_tanh(500.f*xu1) + 0.5f;
            float wd = 0.5f*fast_tanh(500.f*xd1) + 0.5f;
            s1 += wu * (1.f - s1);
            s1 += wd * (-1.f - s1);
        } else {
            if (xu1 > 0.f) s1 = 1.f;
            if (xd1 > 0.f) s1 = -1.f;
        }

        float c = d0*s0 + d1*s1;
        c += __shfl_xor_sync(0xffffffffu, c, 16);
        c += __shfl_xor_sync(0xffffffffu, c, 8);
        c += __shfl_xor_sync(0xffffffffu, c, 4);
        c += __shfl_xor_sync(0xffffffffu, c, 2);
        c += __shfl_xor_sync(0xffffffffu, c, 1);
        if (lane == 0) myrow[t] = c;
    }
    __syncthreads();

    for (int t = tid; t < TT; t += 64) {
        float a = sh_part[0][t] + sh_part[1][t];
        g_bpart[((size_t)b*NBLK_M + blockIdx.x)*TT + t] = a;
    }
}

// ---------------- final: m + b_out ----------------
__global__ void k_final(const float* __restrict__ dec,
                        const float* __restrict__ hraw,
                        const float* __restrict__ mraw,
                        const float* __restrict__ oraw,
                        float* __restrict__ out) {
    int i = blockIdx.x*256 + threadIdx.x;   // 0..16383
    int b = i >> 10, t = i & 1023;
    float acc = 0.f;
#pragma unroll
    for (int k = 0; k < NBLK_M; k++)
        acc += g_bpart[((size_t)b*NBLK_M + k)*TT + t];
    float mv = acc / g_dsum;
    float h = dec[i];
    float hs  = 10.f / (1.f + __expf(-hraw[0]));
    float ms  = 10.f / (1.f + __expf(-mraw[0]));
    float off = -10.f + 20.f / (1.f + __expf(-oraw[0]));
    out[OFF_BOUT + i] = hs*h + ms*mv + off;
    out[OFF_M + i] = mv;
}

// ---------------- launch ----------------
extern "C" void kernel_launch(void* const* d_in, const int* in_sizes, int n_in,
                              void* d_out, int out_size) {
    (void)in_sizes; (void)n_in; (void)out_size;
    const float* enc   = (const float*)d_in[0];
    const float* dec   = (const float*)d_in[1];
    const float* msk   = (const float*)d_in[2];
    const float* mesh  = (const float*)d_in[3];
    const float* dWin  = (const float*)d_in[4];
    const float* dbin  = (const float*)d_in[5];
    const float* dWr   = (const float*)d_in[6];
    const float* dbr   = (const float*)d_in[7];
    const float* dWout = (const float*)d_in[8];
    const float* dbout = (const float*)d_in[9];
    const float* eWs   = (const float*)d_in[10];
    const float* ebs   = (const float*)d_in[11];
    const float* eWm   = (const float*)d_in[12];
    const float* eWc   = (const float*)d_in[13];
    const float* ebm   = (const float*)d_in[14];
    const float* eWo   = (const float*)d_in[15];
    const float* ebo   = (const float*)d_in[16];
    const float* hraw  = (const float*)d_in[17];
    const float* mraw  = (const float*)d_in[18];
    const float* oraw  = (const float*)d_in[19];
    float* out = (float*)d_out;

    // density MLP
    k_dens_in<<<M_PTS, 256>>>(mesh, dWin, dbin);
    dim3 gres(41, 4);
    k_res<<<gres, 256>>>(dWr + 0*HIDN*HIDN, dbr + 0*HIDN, 0);  // x -> y
    k_res<<<gres, 256>>>(dWr + 1*HIDN*HIDN, dbr + 1*HIDN, 1);  // y -> x
    k_res<<<gres, 256>>>(dWr + 2*HIDN*HIDN, dbr + 2*HIDN, 0);  // x -> y
    k_dens_out<<<644, 256>>>(dWout, dbout);
    k_dsum<<<1, 256>>>();

    // encoder + initial states (+ density/mesh output replication)
    k_ctxw<<<BB, 256>>>(enc, msk, eWs, ebs, eWc);
    dim3 ginit(21, BB);
    k_init<<<ginit, 256>>>(mesh, eWm, ebm, eWo, ebo, out);

    // relay scan + final
    dim3 gscan(NBLK_M, BB);
    k_scan<<<gscan, 64>>>(dec, mesh);
    k_final<<<64, 256>>>(dec, hraw, mraw, oraw, out);
}

// round 3
// speedup vs baseline: 1.1536x; 1.1536x over previous
#include <cuda_runtime.h>

#define M_PTS 5151
#define HIDN  256
#define BB    16
#define SS    256
#define TT    1024
#define NBLK_M 41          // ceil(5151/128) scan blocks per batch
#define CUT 0.018f

// Output layout: concatenated (b_out, density, m, initial_states, mesh)
#define OFF_BOUT 0
#define OFF_D    16384                    // 16*1024
#define OFF_M    (OFF_D + BB*M_PTS)       // 98800
#define OFF_IS   (OFF_M + BB*TT)          // 115184
#define OFF_MESH (OFF_IS + BB*M_PTS)      // 197600

// ---------------- scratch (device globals; no allocation) ----------------
__device__ float g_x[5248*HIDN];
__device__ float g_y[5248*HIDN];
__device__ float g_density[M_PTS];
__device__ float g_cwc[BB*HIDN];
__device__ float g_init[BB*M_PTS];
__device__ float g_bpart[BB*NBLK_M*TT];
__device__ float g_dsum;

__device__ __forceinline__ float fast_tanh(float x) {
    float r;
    asm("tanh.approx.f32 %0, %1;" : "=f"(r) : "f"(x));
    return r;
}

// ---------------- density input layer: x = relu(mesh @ Win + bin) --------
__global__ void k_dens_in(const float* __restrict__ mesh,
                          const float* __restrict__ Win,
                          const float* __restrict__ bin) {
    int m = blockIdx.x;
    int j = threadIdx.x;
    float be = mesh[2*m], al = mesh[2*m+1];
    float v = be*Win[j] + al*Win[HIDN+j] + bin[j];
    g_x[m*HIDN + j] = fmaxf(v, 0.f);
}

// ---------------- residual layer: Y = X + relu(X @ W + b) ----------------
// 64x64 tile, BK=16, 128 threads, 8x4 micro-tile, register prefetch.
__global__ void __launch_bounds__(128) k_res(const float* __restrict__ W,
                                             const float* __restrict__ bias,
                                             int flip) {
    const float* X = flip ? g_y : g_x;
    float*       Y = flip ? g_x : g_y;

    __shared__ __align__(16) float As[16][68];   // [k][row]
    __shared__ __align__(16) float Bs[16][64];   // [k][col]

    int bm = blockIdx.x * 64, bn = blockIdx.y * 64;
    int tid = threadIdx.x;
    int tx = tid & 15;        // 16 col groups (4 cols each)
    int ty = tid >> 4;        // 8 row groups (8 rows each)

    float acc[8][4];
#pragma unroll
    for (int i = 0; i < 8; i++)
#pragma unroll
        for (int j = 0; j < 4; j++) acc[i][j] = 0.f;

    // A-load mapping: 64 rows x 16 k per chunk = 1024 floats / 128 thr = 2 float4 (along k)
    int arow = tid & 63;              // row 0..63
    int acol = (tid >> 6) * 8;        // k-offset 0 or 8 (two float4 each)
    int gra  = bm + arow;
    bool av  = gra < M_PTS;
    const float* Xa = X + (size_t)(av ? gra : 0) * HIDN + acol;
    // B-load mapping: 16 k x 64 n = 1024 floats / 128 thr = 2 float4 (along n)
    int bkr0 = tid >> 4;              // k 0..7
    int bc   = (tid & 15) * 4;
    const float* Wb = W + (size_t)bkr0 * HIDN + bn + bc;

    float4 pa0, pa1, pb0, pb1;
    // prefetch chunk 0
    pa0 = av ? *(const float4*)(Xa + 0) : make_float4(0.f,0.f,0.f,0.f);
    pa1 = av ? *(const float4*)(Xa + 4) : make_float4(0.f,0.f,0.f,0.f);
    pb0 = *(const float4*)(Wb);
    pb1 = *(const float4*)(Wb + 8*HIDN);

    for (int k0 = 0; k0 < HIDN; k0 += 16) {
        // store current prefetch to smem
        As[acol+0][arow] = pa0.x;
        As[acol+1][arow] = pa0.y;
        As[acol+2][arow] = pa0.z;
        As[acol+3][arow] = pa0.w;
        As[acol+4][arow] = pa1.x;
        As[acol+5][arow] = pa1.y;
        As[acol+6][arow] = pa1.z;
        As[acol+7][arow] = pa1.w;
        *(float4*)&Bs[bkr0    ][bc] = pb0;
        *(float4*)&Bs[bkr0 + 8][bc] = pb1;
        __syncthreads();

        // prefetch next chunk
        if (k0 + 16 < HIDN) {
            const float* Xn = Xa + k0 + 16;
            const float* Wn = Wb + (size_t)(k0 + 16) * HIDN;
            pa0 = av ? *(const float4*)(Xn + 0) : make_float4(0.f,0.f,0.f,0.f);
            pa1 = av ? *(const float4*)(Xn + 4) : make_float4(0.f,0.f,0.f,0.f);
            pb0 = *(const float4*)(Wn);
            pb1 = *(const float4*)(Wn + 8*HIDN);
        }

#pragma unroll
        for (int kk = 0; kk < 16; kk++) {
            float4 a0 = *(const float4*)&As[kk][ty*8];
            float4 a1 = *(const float4*)&As[kk][ty*8 + 4];
            float4 b0 = *(const float4*)&Bs[kk][tx*4];
            float a[8] = {a0.x,a0.y,a0.z,a0.w,a1.x,a1.y,a1.z,a1.w};
            float b[4] = {b0.x,b0.y,b0.z,b0.w};
#pragma unroll
            for (int i = 0; i < 8; i++)
#pragma unroll
                for (int j = 0; j < 4; j++)
                    acc[i][j] = fmaf(a[i], b[j], acc[i][j]);
        }
        __syncthreads();
    }

    int gc0 = bn + tx*4;
    float4 bz = *(const float4*)&bias[gc0];
    float bv[4] = {bz.x, bz.y, bz.z, bz.w};
#pragma unroll
    for (int i = 0; i < 8; i++) {
        int gr = bm + ty*8 + i;
        if (gr < M_PTS) {
            float4 xv = *(const float4*)&X[gr*HIDN + gc0];
            float4 o;
            o.x = xv.x + fmaxf(acc[i][0] + bv[0], 0.f);
            o.y = xv.y + fmaxf(acc[i][1] + bv[1], 0.f);
            o.z = xv.z + fmaxf(acc[i][2] + bv[2], 0.f);
            o.w = xv.w + fmaxf(acc[i][3] + bv[3], 0.f);
            *(float4*)&Y[gr*HIDN + gc0] = o;
        }
    }
}

// ---------------- density output: sigmoid(x @ Wout + bout) ---------------
__global__ void k_dens_out(const float* __restrict__ Wout,
                           const float* __restrict__ bout) {
    int w = blockIdx.x*8 + (threadIdx.x >> 5);
    int lane = threadIdx.x & 31;
    if (w >= M_PTS) return;
    float acc = 0.f;
#pragma unroll
    for (int i = 0; i < 8; i++)
        acc += g_y[w*HIDN + lane + i*32] * Wout[lane + i*32];
#pragma unroll
    for (int o = 16; o; o >>= 1) acc += __shfl_xor_sync(0xffffffffu, acc, o);
    if (lane == 0) {
        float z = acc + bout[0];
        g_density[w] = 1.f / (1.f + __expf(-z));
    }
}

// ---------------- dsum (deterministic single-block reduce) ---------------
__global__ void k_dsum() {
    __shared__ float s[256];
    int tid = threadIdx.x;
    float a = 0.f;
    for (int i = tid; i < M_PTS; i += 256) a += g_density[i];
    s[tid] = a;
    __syncthreads();
    for (int o = 128; o; o >>= 1) {
        if (tid < o) s[tid] += s[tid + o];
        __syncthreads();
    }
    if (tid == 0) g_dsum = s[0];
}

// ---------------- encoder ctx + ctx @ Wc (fused) ----------------
__global__ void k_ctxw(const float* __restrict__ enc,
                       const float* __restrict__ mask,
                       const float* __restrict__ Ws,
                       const float* __restrict__ bs,
                       const float* __restrict__ Wc) {
    int b = blockIdx.x;
    int j = threadIdx.x;
    __shared__ float se[2*SS];
    __shared__ float sm[SS];
    __shared__ float sctx[HIDN];
    for (int i = j; i < 2*SS; i += 256) se[i] = enc[b*2*SS + i];
    for (int i = j; i < SS;   i += 256) sm[i] = mask[b*SS + i];
    __syncthreads();
    float w0 = Ws[j], w1 = Ws[HIDN + j], bj = bs[j];
    float acc = 0.f, msum = 0.f;
    for (int s = 0; s < SS; s++) {
        float mk = sm[s];
        msum += mk;
        float v = fmaxf(se[2*s]*w0 + se[2*s+1]*w1 + bj, 0.f);
        acc += mk * v;
    }
    sctx[j] = acc / fmaxf(msum, 1.f);
    __syncthreads();
    float a2 = 0.f;
    for (int k = 0; k < HIDN; k++) a2 += sctx[k] * Wc[k*HIDN + j];
    g_cwc[b*HIDN + j] = a2;
}

// ---------------- initial states + density/mesh output replication -------
__global__ void k_init(const float* __restrict__ mesh,
                       const float* __restrict__ Wm,
                       const float* __restrict__ bm,
                       const float* __restrict__ Wo,
                       const float* __restrict__ bo,
                       float* __restrict__ out) {
    int b = blockIdx.y;
    int j = threadIdx.x;
    __shared__ __align__(16) float sW0[HIDN], sW1[HIDN], sW2[HIDN], sWo[HIDN], sC[HIDN];
    sW0[j] = Wm[j];
    sW1[j] = Wm[HIDN + j];
    sW2[j] = Wm[2*HIDN + j];
    sWo[j] = Wo[j];
    sC[j]  = g_cwc[b*HIDN + j] + bm[j];
    __syncthreads();
    int m = blockIdx.x*256 + j;
    if (m >= M_PTS) return;
    float be = mesh[2*m], al = mesh[2*m+1], d = g_density[m];
    const float4* w0 = (const float4*)sW0;
    const float4* w1 = (const float4*)sW1;
    const float4* w2 = (const float4*)sW2;
    const float4* wo = (const float4*)sWo;
    const float4* cc = (const float4*)sC;
    float acc = 0.f;
#pragma unroll 4
    for (int q = 0; q < HIDN/4; q++) {
        float4 a0 = w0[q], a1 = w1[q], a2 = w2[q], ao = wo[q], ac = cc[q];
        acc += fmaxf(be*a0.x + al*a1.x + d*a2.x + ac.x, 0.f) * ao.x;
        acc += fmaxf(be*a0.y + al*a1.y + d*a2.y + ac.y, 0.f) * ao.y;
        acc += fmaxf(be*a0.z + al*a1.z + d*a2.z + ac.z, 0.f) * ao.z;
        acc += fmaxf(be*a0.w + al*a1.w + d*a2.w + ac.w, 0.f) * ao.w;
    }
    float is = tanhf(acc + bo[0]);
    g_init[b*M_PTS + m] = is;
    out[OFF_IS + (size_t)b*M_PTS + m] = is;
    // replicate density + mesh into output
    out[OFF_D + (size_t)b*M_PTS + m] = d;
    ((float2*)out)[(OFF_MESH >> 1) + (size_t)b*M_PTS + m] = make_float2(be, al);
}

// ---------------- relay scan: 64 threads, 2 points/thread ----------------
__global__ void k_scan(const float* __restrict__ dec,
                       const float* __restrict__ mesh) {
    __shared__ float sh_h[TT];
    __shared__ float sh_part[2][TT];
    int b = blockIdx.y;
    int tid = threadIdx.x;        // 0..63
    int m0 = blockIdx.x*128 + tid;
    int m1 = m0 + 64;

    for (int t = tid; t < TT; t += 64) sh_h[t] = dec[b*TT + t];

    bool v0 = m0 < M_PTS, v1 = m1 < M_PTS;
    float be0 = v0 ? mesh[2*m0]   : -2.f;
    float al0 = v0 ? mesh[2*m0+1] :  2.f;
    float d0  = v0 ? g_density[m0] : 0.f;
    float s0  = v0 ? g_init[b*M_PTS + m0] : 0.f;
    float be1 = v1 ? mesh[2*m1]   : -2.f;
    float al1 = v1 ? mesh[2*m1+1] :  2.f;
    float d1  = v1 ? g_density[m1] : 0.f;
    float s1  = v1 ? g_init[b*M_PTS + m1] : 0.f;
    __syncthreads();

    int wid = tid >> 5, lane = tid & 31;
    float* myrow = sh_part[wid];

    for (int t = 0; t < TT; t++) {
        float ht = sh_h[t];

        float xu0 = ht - al0;
        float xd0 = be0 - ht;
        float xu1 = ht - al1;
        float xd1 = be1 - ht;

        bool nearany = (fabsf(xu0) < CUT) | (fabsf(xd0) < CUT) |
                       (fabsf(xu1) < CUT) | (fabsf(xd1) < CUT);
        if (__any_sync(0xffffffffu, nearany)) {
            float wu0 = 0.5f*fast_tanh(500.f*xu0) + 0.5f;
            float wd0 = 0.5f*fast_tanh(500.f*xd0) + 0.5f;
            s0 += wu0 * (1.f - s0);
            s0 += wd0 * (-1.f - s0);
            float wu1 = 0.5f*fast_tanh(500.f*xu1) + 0.5f;
            float wd1 = 0.5f*fast_tanh(500.f*xd1) + 0.5f;
            s1 += wu1 * (1.f - s1);
            s1 += wd1 * (-1.f - s1);
        } else {
            if (xu0 > 0.f) s0 = 1.f;
            if (xd0 > 0.f) s0 = -1.f;
            if (xu1 > 0.f) s1 = 1.f;
            if (xd1 > 0.f) s1 = -1.f;
        }

        float c = d0*s0 + d1*s1;
        c += __shfl_xor_sync(0xffffffffu, c, 16);
        c += __shfl_xor_sync(0xffffffffu, c, 8);
        c += __shfl_xor_sync(0xffffffffu, c, 4);
        c += __shfl_xor_sync(0xffffffffu, c, 2);
        c += __shfl_xor_sync(0xffffffffu, c, 1);
        if (lane == 0) myrow[t] = c;
    }
    __syncthreads();

    for (int t = tid; t < TT; t += 64) {
        float a = sh_part[0][t] + sh_part[1][t];
        g_bpart[((size_t)b*NBLK_M + blockIdx.x)*TT + t] = a;
    }
}

// ---------------- final: m + b_out ----------------
__global__ void k_final(const float* __restrict__ dec,
                        const float* __restrict__ hraw,
                        const float* __restrict__ mraw,
                        const float* __restrict__ oraw,
                        float* __restrict__ out) {
    int i = blockIdx.x*256 + threadIdx.x;   // 0..16383
    int b = i >> 10, t = i & 1023;
    float acc = 0.f;
#pragma unroll
    for (int k = 0; k < NBLK_M; k++)
        acc += g_bpart[((size_t)b*NBLK_M + k)*TT + t];
    float mv = acc / g_dsum;
    float h = dec[i];
    float hs  = 10.f / (1.f + __expf(-hraw[0]));
    float ms  = 10.f / (1.f + __expf(-mraw[0]));
    float off = -10.f + 20.f / (1.f + __expf(-oraw[0]));
    out[OFF_BOUT + i] = hs*h + ms*mv + off;
    out[OFF_M + i] = mv;
}

// ---------------- launch ----------------
extern "C" void kernel_launch(void* const* d_in, const int* in_sizes, int n_in,
                              void* d_out, int out_size) {
    (void)in_sizes; (void)n_in; (void)out_size;
    const float* enc   = (const float*)d_in[0];
    const float* dec   = (const float*)d_in[1];
    const float* msk   = (const float*)d_in[2];
    const float* mesh  = (const float*)d_in[3];
    const float* dWin  = (const float*)d_in[4];
    const float* dbin  = (const float*)d_in[5];
    const float* dWr   = (const float*)d_in[6];
    const float* dbr   = (const float*)d_in[7];
    const float* dWout = (const float*)d_in[8];
    const float* dbout = (const float*)d_in[9];
    const float* eWs   = (const float*)d_in[10];
    const float* ebs   = (const float*)d_in[11];
    const float* eWm   = (const float*)d_in[12];
    const float* eWc   = (const float*)d_in[13];
    const float* ebm   = (const float*)d_in[14];
    const float* eWo   = (const float*)d_in[15];
    const float* ebo   = (const float*)d_in[16];
    const float* hraw  = (const float*)d_in[17];
    const float* mraw  = (const float*)d_in[18];
    const float* oraw  = (const float*)d_in[19];
    float* out = (float*)d_out;

    // density MLP
    k_dens_in<<<M_PTS, 256>>>(mesh, dWin, dbin);
    dim3 gres(81, 4);
    k_res<<<gres, 128>>>(dWr + 0*HIDN*HIDN, dbr + 0*HIDN, 0);  // x -> y
    k_res<<<gres, 128>>>(dWr + 1*HIDN*HIDN, dbr + 1*HIDN, 1);  // y -> x
    k_res<<<gres, 128>>>(dWr + 2*HIDN*HIDN, dbr + 2*HIDN, 0);  // x -> y
    k_dens_out<<<644, 256>>>(dWout, dbout);
    k_dsum<<<1, 256>>>();

    // encoder + initial states (+ density/mesh output replication)
    k_ctxw<<<BB, 256>>>(enc, msk, eWs, ebs, eWc);
    dim3 ginit(21, BB);
    k_init<<<ginit, 256>>>(mesh, eWm, ebm, eWo, ebo, out);

    // relay scan + final
    dim3 gscan(NBLK_M, BB);
    k_scan<<<gscan, 64>>>(dec, mesh);
    k_final<<<64, 256>>>(dec, hraw, mraw, oraw, out);
}